// round 2
// baseline (speedup 1.0000x reference)
#include <cuda_runtime.h>
#include <cuda_bf16.h>
#include <math.h>

#define NROWS 8192
#define DDIM  512
#define EPS   1e-5f

// ---------------- scratch (device globals; no allocation allowed) ----------------
__device__ float g_ln1[NROWS * DDIM];
__device__ float g_ln2[NROWS * DDIM];
__device__ float g_q  [NROWS * DDIM];
__device__ float g_k  [NROWS * DDIM];
__device__ float g_xw [NROWS * DDIM];
__device__ float g_h1 [NROWS * DDIM];
__device__ float g_h2 [NROWS * DDIM];
__device__ int   g_batch[NROWS];
__device__ int   g_segs[NROWS];
__device__ int   g_sege[NROWS];

// ---------------- reductions ----------------
__device__ __forceinline__ float warpSum(float v) {
    #pragma unroll
    for (int o = 16; o > 0; o >>= 1) v += __shfl_xor_sync(0xffffffffu, v, o);
    return v;
}
__device__ __forceinline__ float warpMax(float v) {
    #pragma unroll
    for (int o = 16; o > 0; o >>= 1) v = fmaxf(v, __shfl_xor_sync(0xffffffffu, v, o));
    return v;
}
// block of 256 threads
__device__ float blockSum256(float v) {
    __shared__ float sh[8];
    int lane = threadIdx.x & 31, w = threadIdx.x >> 5;
    v = warpSum(v);
    if (lane == 0) sh[w] = v;
    __syncthreads();
    float t = (lane < 8) ? sh[lane] : 0.0f;
    t = warpSum(t);
    __shared__ float bres;
    if (threadIdx.x == 0) bres = t;
    __syncthreads();
    float r = bres;
    __syncthreads();
    return r;
}
__device__ float blockMax256(float v) {
    __shared__ float sh[8];
    int lane = threadIdx.x & 31, w = threadIdx.x >> 5;
    v = warpMax(v);
    if (lane == 0) sh[w] = v;
    __syncthreads();
    float t = (lane < 8) ? sh[lane] : -3.0e38f;
    t = warpMax(t);
    __shared__ float bres;
    if (threadIdx.x == 0) bres = t;
    __syncthreads();
    float r = bres;
    __syncthreads();
    return r;
}

// ---------------- batch dtype handling + segment bounds ----------------
// If batch came over as int64 (little-endian), the int32 word at index 8191 is
// the HIGH word of element 4095 -> 0. If int32, word 8191 is the max batch id
// (sorted, ~63) -> nonzero. Branch per element; never read OOB for int32.
__global__ void batch_convert_kernel(const int* __restrict__ p) {
    int i = blockIdx.x * blockDim.x + threadIdx.x;
    if (i >= NROWS) return;
    int is64 = (__ldg(p + (NROWS - 1)) == 0);
    g_batch[i] = is64 ? __ldg(p + 2 * i) : __ldg(p + i);
}

__global__ void seg_kernel() {
    int i = blockIdx.x * blockDim.x + threadIdx.x;
    if (i >= NROWS) return;
    int v = g_batch[i];
    int lo = 0, hi = NROWS;
    while (lo < hi) { int mid = (lo + hi) >> 1; if (g_batch[mid] < v) lo = mid + 1; else hi = mid; }
    g_segs[i] = lo;
    lo = 0; hi = NROWS;
    while (lo < hi) { int mid = (lo + hi) >> 1; if (g_batch[mid] <= v) lo = mid + 1; else hi = mid; }
    g_sege[i] = lo;
}

// ---------------- LayerNorm: one block (256 thr) per row, D=512 ----------------
__global__ __launch_bounds__(256) void ln_kernel(const float* __restrict__ x,
                                                 const float* __restrict__ w,
                                                 const float* __restrict__ b,
                                                 float* __restrict__ y) {
    int row = blockIdx.x, t = threadIdx.x;
    const float* xr = x + (size_t)row * DDIM;
    float v0 = xr[t], v1 = xr[t + 256];
    float mu = blockSum256(v0 + v1) * (1.0f / DDIM);
    float d0 = v0 - mu, d1 = v1 - mu;
    float var = blockSum256(d0 * d0 + d1 * d1) * (1.0f / DDIM);
    float r = rsqrtf(var + EPS);
    float* yr = y + (size_t)row * DDIM;
    yr[t]       = d0 * r * w[t]       + b[t];
    yr[t + 256] = d1 * r * w[t + 256] + b[t + 256];
}

// ---------------- fp32 NT GEMM: C[M,512] = A[M,512] @ B[512,512]^T (+bias)(+SiLU) ----------------
// BM=128, BN=64, BK=16, 256 threads, 8x4 microtile.
__global__ __launch_bounds__(256) void gemm_nt(const float* __restrict__ A,
                                               const float* __restrict__ B,
                                               const float* __restrict__ bias,
                                               float* __restrict__ C,
                                               int act) {
    __shared__ float As[16][132];
    __shared__ float Bs[16][68];
    const int bm = blockIdx.y * 128;
    const int bn = blockIdx.x * 64;
    const int tid = threadIdx.x;
    const int tx = tid & 15;        // 0..15 -> 4 cols each
    const int ty = tid >> 4;        // 0..15 -> 8 rows each
    const int arow = tid >> 2;      // 0..63
    const int ak   = (tid & 3) << 2;

    float acc[8][4];
    #pragma unroll
    for (int i = 0; i < 8; i++)
        #pragma unroll
        for (int j = 0; j < 4; j++) acc[i][j] = 0.0f;

    for (int k0 = 0; k0 < DDIM; k0 += 16) {
        #pragma unroll
        for (int h = 0; h < 2; h++) {
            int r = arow + h * 64;
            float4 v = *(const float4*)(A + (size_t)(bm + r) * DDIM + k0 + ak);
            As[ak + 0][r] = v.x; As[ak + 1][r] = v.y;
            As[ak + 2][r] = v.z; As[ak + 3][r] = v.w;
        }
        {
            float4 v = *(const float4*)(B + (size_t)(bn + arow) * DDIM + k0 + ak);
            Bs[ak + 0][arow] = v.x; Bs[ak + 1][arow] = v.y;
            Bs[ak + 2][arow] = v.z; Bs[ak + 3][arow] = v.w;
        }
        __syncthreads();
        #pragma unroll
        for (int k = 0; k < 16; k++) {
            float a[8], bb[4];
            #pragma unroll
            for (int i = 0; i < 8; i++) a[i] = As[k][ty * 8 + i];
            #pragma unroll
            for (int j = 0; j < 4; j++) bb[j] = Bs[k][tx * 4 + j];
            #pragma unroll
            for (int i = 0; i < 8; i++)
                #pragma unroll
                for (int j = 0; j < 4; j++) acc[i][j] = fmaf(a[i], bb[j], acc[i][j]);
        }
        __syncthreads();
    }

    #pragma unroll
    for (int i = 0; i < 8; i++) {
        int row = bm + ty * 8 + i;
        #pragma unroll
        for (int j = 0; j < 4; j++) {
            int col = bn + tx * 4 + j;
            float v = acc[i][j];
            if (bias) v += bias[col];
            if (act)  v = v / (1.0f + expf(-v));   // SiLU
            C[(size_t)row * DDIM + col] = v;
        }
    }
}

// ---------------- attention: per-row dot + masked softmax ----------------
// One block (256 thr) per row i. Writes attn[i, s:e] (rest pre-zeroed).
__global__ __launch_bounds__(256) void attn_softmax_kernel(float* __restrict__ attn) {
    int i = blockIdx.x, tid = threadIdx.x;
    __shared__ float qs[DDIM];
    qs[tid]       = g_q[(size_t)i * DDIM + tid];
    qs[tid + 256] = g_q[(size_t)i * DDIM + tid + 256];
    __syncthreads();

    int s = g_segs[i], e = g_sege[i];
    float* row = attn + (size_t)i * NROWS;

    // phase 1: dots + local max (reference: max over dot*mask includes 0)
    float m = 0.0f;
    for (int j = s + tid; j < e; j += 256) {
        const float* kr = g_k + (size_t)j * DDIM;
        float d = 0.0f;
        #pragma unroll 8
        for (int c = 0; c < DDIM; c += 4) {
            float4 kv = *(const float4*)(kr + c);
            d = fmaf(qs[c], kv.x, d);
            d = fmaf(qs[c + 1], kv.y, d);
            d = fmaf(qs[c + 2], kv.z, d);
            d = fmaf(qs[c + 3], kv.w, d);
        }
        row[j] = d;
        m = fmaxf(m, d);
    }
    m = blockMax256(m);
    m = fmaxf(m, 0.0f);

    // phase 2: exp + sum
    float ssum = 0.0f;
    for (int j = s + tid; j < e; j += 256) {
        float ev = expf(row[j] - m);
        ssum += ev;
        row[j] = ev;
    }
    ssum = blockSum256(ssum);
    float inv = 1.0f / ssum;

    // phase 3: normalize
    for (int j = s + tid; j < e; j += 256) row[j] *= inv;
}

// ---------------- x_weighted = attn @ x_conf (block-diagonal only) ----------------
// One block (128 thr) per row; each thread owns 4 contiguous columns.
__global__ __launch_bounds__(128) void attn_apply_kernel(const float* __restrict__ attn,
                                                         const float* __restrict__ xc,
                                                         float* __restrict__ xw) {
    int i = blockIdx.x, tid = threadIdx.x;
    int s = g_segs[i], e = g_sege[i];
    const float* row = attn + (size_t)i * NROWS;
    float a0 = 0.f, a1 = 0.f, a2 = 0.f, a3 = 0.f;
    for (int j = s; j < e; j++) {
        float a = __ldg(row + j);
        float4 v = *(const float4*)(xc + (size_t)j * DDIM + tid * 4);
        a0 = fmaf(a, v.x, a0);
        a1 = fmaf(a, v.y, a1);
        a2 = fmaf(a, v.z, a2);
        a3 = fmaf(a, v.w, a3);
    }
    float4 o = make_float4(a0, a1, a2, a3);
    *(float4*)(xw + (size_t)i * DDIM + tid * 4) = o;
}

// ---------------- launch ----------------
extern "C" void kernel_launch(void* const* d_in, const int* in_sizes, int n_in,
                              void* d_out, int out_size) {
    const float* x_mole  = (const float*)d_in[0];
    const float* x_conf  = (const float*)d_in[1];
    const float* W1      = (const float*)d_in[2];
    const float* W2      = (const float*)d_in[3];
    const float* phi1_w  = (const float*)d_in[4];
    const float* phi1_b  = (const float*)d_in[5];
    const float* phi2_w  = (const float*)d_in[6];
    const float* phi2_b  = (const float*)d_in[7];
    const float* rho_w1  = (const float*)d_in[8];
    const float* rho_b1  = (const float*)d_in[9];
    const float* rho_w2  = (const float*)d_in[10];
    const float* rho_b2  = (const float*)d_in[11];
    const float* rho_ln_w = (const float*)d_in[12];
    const float* rho_ln_b = (const float*)d_in[13];
    const int*   batch   = (const int*)d_in[14];

    float* out_enc  = (float*)d_out;                        // x_encoded [N, D]
    float* out_attn = (float*)d_out + (size_t)NROWS * DDIM; // attn [N, N]

    // Resolve device-global scratch addresses (host code may NOT take the
    // address of a __device__ symbol directly -- that was the Round-1 bug).
    float *ln1, *ln2, *q, *k, *xw, *h1, *h2;
    cudaGetSymbolAddress((void**)&ln1, g_ln1);
    cudaGetSymbolAddress((void**)&ln2, g_ln2);
    cudaGetSymbolAddress((void**)&q,   g_q);
    cudaGetSymbolAddress((void**)&k,   g_k);
    cudaGetSymbolAddress((void**)&xw,  g_xw);
    cudaGetSymbolAddress((void**)&h1,  g_h1);
    cudaGetSymbolAddress((void**)&h2,  g_h2);

    // segment metadata
    batch_convert_kernel<<<(NROWS + 255) / 256, 256>>>(batch);
    seg_kernel<<<(NROWS + 255) / 256, 256>>>();

    // LayerNorm inputs
    ln_kernel<<<NROWS, 256>>>(x_mole, phi1_w, phi1_b, ln1);
    ln_kernel<<<NROWS, 256>>>(x_conf, phi2_w, phi2_b, ln2);

    // q / k projections
    dim3 ggrid(DDIM / 64, NROWS / 128);
    gemm_nt<<<ggrid, 256>>>(ln1, W1, nullptr, q, 0);
    gemm_nt<<<ggrid, 256>>>(ln2, W2, nullptr, k, 0);

    // attn: zero full matrix then fill block-diagonal entries
    cudaMemsetAsync(out_attn, 0, (size_t)NROWS * NROWS * sizeof(float));
    attn_softmax_kernel<<<NROWS, 256>>>(out_attn);
    attn_apply_kernel<<<NROWS, 128>>>(out_attn, x_conf, xw);

    // rho MLP
    gemm_nt<<<ggrid, 256>>>(xw, rho_w1, rho_b1, h1, 1);
    gemm_nt<<<ggrid, 256>>>(h1, rho_w2, rho_b2, h2, 1);

    // final LayerNorm straight into output
    ln_kernel<<<NROWS, 256>>>(h2, rho_ln_w, rho_ln_b, out_enc);
}

// round 3
// speedup vs baseline: 1.2441x; 1.2441x over previous
#include <cuda_runtime.h>
#include <cuda_bf16.h>
#include <mma.h>
#include <math.h>

using namespace nvcuda;

#define NROWS 8192
#define DDIM  512
#define EPS   1e-5f

// ---------------- scratch (device globals; no allocation allowed) ----------------
__device__ float g_q  [NROWS * DDIM];       // gemm raw outputs (reused)
__device__ float g_k  [NROWS * DDIM];
__device__ __nv_bfloat16 g_sh[NROWS * DDIM]; // activation split hi (reused along the chain)
__device__ __nv_bfloat16 g_sl[NROWS * DDIM]; // activation split lo
__device__ __nv_bfloat16 g_wh[4][DDIM * DDIM]; // weight splits hi
__device__ __nv_bfloat16 g_wl[4][DDIM * DDIM]; // weight splits lo
__device__ int   g_batch[NROWS];
__device__ int   g_segs[NROWS];
__device__ int   g_sege[NROWS];

// ---------------- reductions ----------------
__device__ __forceinline__ float warpSum(float v) {
    #pragma unroll
    for (int o = 16; o > 0; o >>= 1) v += __shfl_xor_sync(0xffffffffu, v, o);
    return v;
}
__device__ float blockSum256(float v) {
    __shared__ float sh[8];
    int lane = threadIdx.x & 31, w = threadIdx.x >> 5;
    v = warpSum(v);
    if (lane == 0) sh[w] = v;
    __syncthreads();
    float t = (lane < 8) ? sh[lane] : 0.0f;
    t = warpSum(t);
    __shared__ float bres;
    if (threadIdx.x == 0) bres = t;
    __syncthreads();
    float r = bres;
    __syncthreads();
    return r;
}

// ---------------- batch dtype handling + segment bounds ----------------
__global__ void batch_convert_kernel(const int* __restrict__ p) {
    int i = blockIdx.x * blockDim.x + threadIdx.x;
    if (i >= NROWS) return;
    int is64 = (__ldg(p + (NROWS - 1)) == 0);
    g_batch[i] = is64 ? __ldg(p + 2 * i) : __ldg(p + i);
}

__global__ void seg_kernel() {
    int i = blockIdx.x * blockDim.x + threadIdx.x;
    if (i >= NROWS) return;
    int v = g_batch[i];
    int lo = 0, hi = NROWS;
    while (lo < hi) { int mid = (lo + hi) >> 1; if (g_batch[mid] < v) lo = mid + 1; else hi = mid; }
    g_segs[i] = lo;
    lo = 0; hi = NROWS;
    while (lo < hi) { int mid = (lo + hi) >> 1; if (g_batch[mid] <= v) lo = mid + 1; else hi = mid; }
    g_sege[i] = lo;
}

// ---------------- split helpers ----------------
__device__ __forceinline__ void split2(float v, __nv_bfloat16& hi, __nv_bfloat16& lo) {
    hi = __float2bfloat16(v);
    lo = __float2bfloat16(v - __bfloat162float(hi));
}

// weight fp32 -> bf16 hi/lo
__global__ __launch_bounds__(256) void w_split_kernel(const float* __restrict__ w,
                                                      __nv_bfloat16* __restrict__ wh,
                                                      __nv_bfloat16* __restrict__ wl) {
    int i = blockIdx.x * 256 + threadIdx.x;
    __nv_bfloat16 h, l;
    split2(w[i], h, l);
    wh[i] = h; wl[i] = l;
}

// ---------------- LayerNorm producing bf16 split ----------------
__global__ __launch_bounds__(256) void ln_split_kernel(const float* __restrict__ x,
                                                       const float* __restrict__ w,
                                                       const float* __restrict__ b,
                                                       __nv_bfloat16* __restrict__ sh_,
                                                       __nv_bfloat16* __restrict__ sl_) {
    int row = blockIdx.x, t = threadIdx.x;
    const float* xr = x + (size_t)row * DDIM;
    float v0 = xr[t], v1 = xr[t + 256];
    float mu = blockSum256(v0 + v1) * (1.0f / DDIM);
    float d0 = v0 - mu, d1 = v1 - mu;
    float var = blockSum256(d0 * d0 + d1 * d1) * (1.0f / DDIM);
    float r = rsqrtf(var + EPS);
    float y0 = d0 * r * w[t]       + b[t];
    float y1 = d1 * r * w[t + 256] + b[t + 256];
    __nv_bfloat16 h, l;
    size_t base = (size_t)row * DDIM;
    split2(y0, h, l); sh_[base + t] = h;       sl_[base + t] = l;
    split2(y1, h, l); sh_[base + t + 256] = h; sl_[base + t + 256] = l;
}

// ---------------- plain LayerNorm (final) ----------------
__global__ __launch_bounds__(256) void ln_kernel(const float* __restrict__ x,
                                                 const float* __restrict__ w,
                                                 const float* __restrict__ b,
                                                 float* __restrict__ y) {
    int row = blockIdx.x, t = threadIdx.x;
    const float* xr = x + (size_t)row * DDIM;
    float v0 = xr[t], v1 = xr[t + 256];
    float mu = blockSum256(v0 + v1) * (1.0f / DDIM);
    float d0 = v0 - mu, d1 = v1 - mu;
    float var = blockSum256(d0 * d0 + d1 * d1) * (1.0f / DDIM);
    float r = rsqrtf(var + EPS);
    float* yr = y + (size_t)row * DDIM;
    yr[t]       = d0 * r * w[t]       + b[t];
    yr[t + 256] = d1 * r * w[t + 256] + b[t + 256];
}

// ---------------- bf16-split wmma GEMM: C[M,512] = A @ B^T (fp32 accum) ----------------
// C = Ah@Bh^T + Ah@Bl^T + Al@Bh^T. Block tile 128x128, 8 warps (4m x 2n),
// warp tile 32x64, BK=32. smem 40KB.
__global__ __launch_bounds__(256) void gemm_wmma(const __nv_bfloat16* __restrict__ Ah,
                                                 const __nv_bfloat16* __restrict__ Al,
                                                 const __nv_bfloat16* __restrict__ Bh,
                                                 const __nv_bfloat16* __restrict__ Bl,
                                                 float* __restrict__ C) {
    __shared__ __nv_bfloat16 sAh[128 * 40], sAl[128 * 40];
    __shared__ __nv_bfloat16 sBh[128 * 40], sBl[128 * 40];
    const int tid = threadIdx.x;
    const int wid = tid >> 5;
    const int wm = wid >> 1;          // 0..3
    const int wn = wid & 1;           // 0..1
    const int bm = blockIdx.y * 128;
    const int bn = blockIdx.x * 128;
    const int row = tid >> 2;         // 0..63
    const int kc  = (tid & 3) * 8;    // 0,8,16,24

    wmma::fragment<wmma::accumulator, 16, 16, 16, float> acc[2][4];
    #pragma unroll
    for (int mi = 0; mi < 2; mi++)
        #pragma unroll
        for (int ni = 0; ni < 4; ni++) wmma::fill_fragment(acc[mi][ni], 0.0f);

    for (int k0 = 0; k0 < DDIM; k0 += 32) {
        uint4 vah[2], val_[2], vbh[2], vbl[2];
        #pragma unroll
        for (int h = 0; h < 2; h++) {
            size_t aoff = (size_t)(bm + row + h * 64) * DDIM + k0 + kc;
            size_t boff = (size_t)(bn + row + h * 64) * DDIM + k0 + kc;
            vah[h]  = *(const uint4*)(Ah + aoff);
            val_[h] = *(const uint4*)(Al + aoff);
            vbh[h]  = *(const uint4*)(Bh + boff);
            vbl[h]  = *(const uint4*)(Bl + boff);
        }
        __syncthreads();                 // previous iter's compute done
        #pragma unroll
        for (int h = 0; h < 2; h++) {
            int so = (row + h * 64) * 40 + kc;
            *(uint4*)(sAh + so) = vah[h];
            *(uint4*)(sAl + so) = val_[h];
            *(uint4*)(sBh + so) = vbh[h];
            *(uint4*)(sBl + so) = vbl[h];
        }
        __syncthreads();
        #pragma unroll
        for (int kk = 0; kk < 32; kk += 16) {
            wmma::fragment<wmma::matrix_a, 16, 16, 16, __nv_bfloat16, wmma::row_major> fah[2], fal[2];
            #pragma unroll
            for (int mi = 0; mi < 2; mi++) {
                wmma::load_matrix_sync(fah[mi], sAh + (wm * 32 + mi * 16) * 40 + kk, 40);
                wmma::load_matrix_sync(fal[mi], sAl + (wm * 32 + mi * 16) * 40 + kk, 40);
            }
            #pragma unroll
            for (int ni = 0; ni < 4; ni++) {
                wmma::fragment<wmma::matrix_b, 16, 16, 16, __nv_bfloat16, wmma::col_major> fbh, fbl;
                wmma::load_matrix_sync(fbh, sBh + (wn * 64 + ni * 16) * 40 + kk, 40);
                wmma::load_matrix_sync(fbl, sBl + (wn * 64 + ni * 16) * 40 + kk, 40);
                #pragma unroll
                for (int mi = 0; mi < 2; mi++) {
                    wmma::mma_sync(acc[mi][ni], fah[mi], fbh, acc[mi][ni]);
                    wmma::mma_sync(acc[mi][ni], fah[mi], fbl, acc[mi][ni]);
                    wmma::mma_sync(acc[mi][ni], fal[mi], fbh, acc[mi][ni]);
                }
            }
        }
    }
    #pragma unroll
    for (int mi = 0; mi < 2; mi++)
        #pragma unroll
        for (int ni = 0; ni < 4; ni++)
            wmma::store_matrix_sync(C + (size_t)(bm + wm * 32 + mi * 16) * DDIM + bn + wn * 64 + ni * 16,
                                    acc[mi][ni], DDIM, wmma::mem_row_major);
}

// ---------------- GEMM epilogues: bias + SiLU ----------------
// writes split only (h1 path)
__global__ __launch_bounds__(256) void epi_silu_split(const float* __restrict__ C,
                                                      const float* __restrict__ bias,
                                                      __nv_bfloat16* __restrict__ sh_,
                                                      __nv_bfloat16* __restrict__ sl_) {
    int i = blockIdx.x * 256 + threadIdx.x;
    float v = C[i] + bias[i & (DDIM - 1)];
    v = v / (1.0f + expf(-v));
    __nv_bfloat16 h, l;
    split2(v, h, l);
    sh_[i] = h; sl_[i] = l;
}
// in-place fp32 (h2 path, feeds final LN)
__global__ __launch_bounds__(256) void epi_silu_inplace(float* __restrict__ C,
                                                        const float* __restrict__ bias) {
    int i = blockIdx.x * 256 + threadIdx.x;
    float v = C[i] + bias[i & (DDIM - 1)];
    C[i] = v / (1.0f + expf(-v));
}

// ---------------- attention softmax: warp per row, 8 rows per block ----------------
__global__ __launch_bounds__(256) void attn_softmax8(const float* __restrict__ q,
                                                     const float* __restrict__ kmat,
                                                     float* __restrict__ attn) {
    int wid = threadIdx.x >> 5, lane = threadIdx.x & 31;
    int i = blockIdx.x * 8 + wid;
    const float* qr = q + (size_t)i * DDIM + lane * 16;
    float4 q0 = *(const float4*)(qr + 0);
    float4 q1 = *(const float4*)(qr + 4);
    float4 q2 = *(const float4*)(qr + 8);
    float4 q3 = *(const float4*)(qr + 12);

    int s = g_segs[i], e = g_sege[i];
    float* row = attn + (size_t)i * NROWS;

    float m = 0.0f;
    for (int j = s; j < e; j++) {
        const float* kr = kmat + (size_t)j * DDIM + lane * 16;
        float4 k0 = *(const float4*)(kr + 0);
        float4 k1 = *(const float4*)(kr + 4);
        float4 k2 = *(const float4*)(kr + 8);
        float4 k3 = *(const float4*)(kr + 12);
        float d = q0.x * k0.x;
        d = fmaf(q0.y, k0.y, d); d = fmaf(q0.z, k0.z, d); d = fmaf(q0.w, k0.w, d);
        d = fmaf(q1.x, k1.x, d); d = fmaf(q1.y, k1.y, d); d = fmaf(q1.z, k1.z, d); d = fmaf(q1.w, k1.w, d);
        d = fmaf(q2.x, k2.x, d); d = fmaf(q2.y, k2.y, d); d = fmaf(q2.z, k2.z, d); d = fmaf(q2.w, k2.w, d);
        d = fmaf(q3.x, k3.x, d); d = fmaf(q3.y, k3.y, d); d = fmaf(q3.z, k3.z, d); d = fmaf(q3.w, k3.w, d);
        d = warpSum(d);                 // all lanes hold full dot
        if (lane == 0) row[j] = d;
        m = fmaxf(m, d);
    }
    __syncwarp();
    m = fmaxf(m, 0.0f);                 // reference: max includes masked zeros

    float ssum = 0.0f;
    for (int j = s + lane; j < e; j += 32) {
        float ev = expf(row[j] - m);
        ssum += ev;
        row[j] = ev;
    }
    ssum = warpSum(ssum);
    float inv = 1.0f / ssum;
    for (int j = s + lane; j < e; j += 32) row[j] *= inv;
}

// ---------------- x_weighted = attn @ x_conf; writes bf16 split ----------------
__global__ __launch_bounds__(256) void attn_apply8(const float* __restrict__ attn,
                                                   const float* __restrict__ xc,
                                                   __nv_bfloat16* __restrict__ sh_,
                                                   __nv_bfloat16* __restrict__ sl_) {
    int wid = threadIdx.x >> 5, lane = threadIdx.x & 31;
    int i = blockIdx.x * 8 + wid;
    int s = g_segs[i], e = g_sege[i];
    const float* row = attn + (size_t)i * NROWS;
    float acc[16];
    #pragma unroll
    for (int c = 0; c < 16; c++) acc[c] = 0.0f;
    for (int j = s; j < e; j++) {
        float a = __ldg(row + j);       // warp-uniform broadcast
        const float* xr = xc + (size_t)j * DDIM + lane * 16;
        float4 v0 = *(const float4*)(xr + 0);
        float4 v1 = *(const float4*)(xr + 4);
        float4 v2 = *(const float4*)(xr + 8);
        float4 v3 = *(const float4*)(xr + 12);
        acc[0]  = fmaf(a, v0.x, acc[0]);  acc[1]  = fmaf(a, v0.y, acc[1]);
        acc[2]  = fmaf(a, v0.z, acc[2]);  acc[3]  = fmaf(a, v0.w, acc[3]);
        acc[4]  = fmaf(a, v1.x, acc[4]);  acc[5]  = fmaf(a, v1.y, acc[5]);
        acc[6]  = fmaf(a, v1.z, acc[6]);  acc[7]  = fmaf(a, v1.w, acc[7]);
        acc[8]  = fmaf(a, v2.x, acc[8]);  acc[9]  = fmaf(a, v2.y, acc[9]);
        acc[10] = fmaf(a, v2.z, acc[10]); acc[11] = fmaf(a, v2.w, acc[11]);
        acc[12] = fmaf(a, v3.x, acc[12]); acc[13] = fmaf(a, v3.y, acc[13]);
        acc[14] = fmaf(a, v3.z, acc[14]); acc[15] = fmaf(a, v3.w, acc[15]);
    }
    size_t base = (size_t)i * DDIM + lane * 16;
    #pragma unroll
    for (int c = 0; c < 16; c++) {
        __nv_bfloat16 h, l;
        split2(acc[c], h, l);
        sh_[base + c] = h; sl_[base + c] = l;
    }
}

// ---------------- launch ----------------
extern "C" void kernel_launch(void* const* d_in, const int* in_sizes, int n_in,
                              void* d_out, int out_size) {
    const float* x_mole  = (const float*)d_in[0];
    const float* x_conf  = (const float*)d_in[1];
    const float* W1      = (const float*)d_in[2];
    const float* W2      = (const float*)d_in[3];
    const float* phi1_w  = (const float*)d_in[4];
    const float* phi1_b  = (const float*)d_in[5];
    const float* phi2_w  = (const float*)d_in[6];
    const float* phi2_b  = (const float*)d_in[7];
    const float* rho_w1  = (const float*)d_in[8];
    const float* rho_b1  = (const float*)d_in[9];
    const float* rho_w2  = (const float*)d_in[10];
    const float* rho_b2  = (const float*)d_in[11];
    const float* rho_ln_w = (const float*)d_in[12];
    const float* rho_ln_b = (const float*)d_in[13];
    const int*   batch   = (const int*)d_in[14];

    float* out_enc  = (float*)d_out;                        // x_encoded [N, D]
    float* out_attn = (float*)d_out + (size_t)NROWS * DDIM; // attn [N, N]

    float *q, *k;
    __nv_bfloat16 *sh_, *sl_, *wh, *wl;
    cudaGetSymbolAddress((void**)&q,   g_q);
    cudaGetSymbolAddress((void**)&k,   g_k);
    cudaGetSymbolAddress((void**)&sh_, g_sh);
    cudaGetSymbolAddress((void**)&sl_, g_sl);
    cudaGetSymbolAddress((void**)&wh,  g_wh);
    cudaGetSymbolAddress((void**)&wl,  g_wl);
    const size_t WSZ = (size_t)DDIM * DDIM;

    // segment metadata
    batch_convert_kernel<<<(NROWS + 255) / 256, 256>>>(batch);
    seg_kernel<<<(NROWS + 255) / 256, 256>>>();

    // weight splits (fp32 -> bf16 hi/lo), 4 weights
    int wgrid = (int)(WSZ / 256);
    w_split_kernel<<<wgrid, 256>>>(W1,     wh + 0 * WSZ, wl + 0 * WSZ);
    w_split_kernel<<<wgrid, 256>>>(W2,     wh + 1 * WSZ, wl + 1 * WSZ);
    w_split_kernel<<<wgrid, 256>>>(rho_w1, wh + 2 * WSZ, wl + 2 * WSZ);
    w_split_kernel<<<wgrid, 256>>>(rho_w2, wh + 3 * WSZ, wl + 3 * WSZ);

    // zero the attn output early (block-diagonal fill comes later)
    cudaMemsetAsync(out_attn, 0, (size_t)NROWS * NROWS * sizeof(float));

    dim3 ggrid(DDIM / 128, NROWS / 128);

    // q = LN(x_mole) @ W1^T
    ln_split_kernel<<<NROWS, 256>>>(x_mole, phi1_w, phi1_b, sh_, sl_);
    gemm_wmma<<<ggrid, 256>>>(sh_, sl_, wh + 0 * WSZ, wl + 0 * WSZ, q);
    // k = LN(x_conf) @ W2^T
    ln_split_kernel<<<NROWS, 256>>>(x_conf, phi2_w, phi2_b, sh_, sl_);
    gemm_wmma<<<ggrid, 256>>>(sh_, sl_, wh + 1 * WSZ, wl + 1 * WSZ, k);

    // masked softmax into d_out attn, then x_weighted (as bf16 split)
    attn_softmax8<<<NROWS / 8, 256>>>(q, k, out_attn);
    attn_apply8<<<NROWS / 8, 256>>>(out_attn, x_conf, sh_, sl_);

    // rho MLP
    int egrid = (int)((size_t)NROWS * DDIM / 256);
    gemm_wmma<<<ggrid, 256>>>(sh_, sl_, wh + 2 * WSZ, wl + 2 * WSZ, q);   // raw h1
    epi_silu_split<<<egrid, 256>>>(q, rho_b1, sh_, sl_);                  // SiLU + split
    gemm_wmma<<<ggrid, 256>>>(sh_, sl_, wh + 3 * WSZ, wl + 3 * WSZ, k);   // raw h2
    epi_silu_inplace<<<egrid, 256>>>(k, rho_b2);                          // SiLU fp32

    // final LayerNorm straight into output
    ln_kernel<<<NROWS, 256>>>(k, rho_ln_w, rho_ln_b, out_enc);
}

// round 5
// speedup vs baseline: 1.3621x; 1.0948x over previous
#include <cuda_runtime.h>
#include <cuda_bf16.h>
#include <math.h>
#include <stdint.h>

#define NROWS 8192
#define DDIM  512
#define EPS   1e-5f

// ================= PTX helpers (sm_103 base-target safe: no tcgen05) =================
__device__ __forceinline__ uint32_t smem_u32(const void* p) {
    uint32_t a;
    asm("{ .reg .u64 t; cvta.to.shared.u64 t, %1; cvt.u32.u64 %0, t; }" : "=r"(a) : "l"(p));
    return a;
}
#define CP_ASYNC16(smem, gptr) \
    asm volatile("cp.async.cg.shared.global [%0], [%1], 16;" :: "r"(smem), "l"(gptr))
#define CP_COMMIT() asm volatile("cp.async.commit_group;" ::: "memory")
#define CP_WAIT(n)  asm volatile("cp.async.wait_group %0;" :: "n"(n) : "memory")

#define LDMX4(r, addr) \
    asm volatile("ldmatrix.sync.aligned.m8n8.x4.shared.b16 {%0,%1,%2,%3}, [%4];" \
        : "=r"((r)[0]), "=r"((r)[1]), "=r"((r)[2]), "=r"((r)[3]) : "r"(addr))

#define MMA16816(d, a, b0, b1) \
    asm volatile("mma.sync.aligned.m16n8k16.row.col.f32.bf16.bf16.f32 " \
        "{%0,%1,%2,%3}, {%4,%5,%6,%7}, {%8,%9}, {%0,%1,%2,%3};" \
        : "+f"((d)[0]), "+f"((d)[1]), "+f"((d)[2]), "+f"((d)[3]) \
        : "r"((a)[0]), "r"((a)[1]), "r"((a)[2]), "r"((a)[3]), "r"(b0), "r"(b1))

// ================= scratch =================
__device__ float g_q  [NROWS * DDIM];
__device__ float g_k  [NROWS * DDIM];
__device__ __nv_bfloat16 g_sh1[NROWS * DDIM];
__device__ __nv_bfloat16 g_sl1[NROWS * DDIM];
__device__ __nv_bfloat16 g_sh2[NROWS * DDIM];
__device__ __nv_bfloat16 g_sl2[NROWS * DDIM];
__device__ __nv_bfloat16 g_wh[4][DDIM * DDIM];
__device__ __nv_bfloat16 g_wl[4][DDIM * DDIM];
__device__ int   g_batch[NROWS];
__device__ int   g_segs[NROWS];
__device__ int   g_sege[NROWS];

// ================= reductions =================
__device__ __forceinline__ float warpSum(float v) {
    #pragma unroll
    for (int o = 16; o > 0; o >>= 1) v += __shfl_xor_sync(0xffffffffu, v, o);
    return v;
}
__device__ float blockSum256(float v) {
    __shared__ float sh[8];
    int lane = threadIdx.x & 31, w = threadIdx.x >> 5;
    v = warpSum(v);
    if (lane == 0) sh[w] = v;
    __syncthreads();
    float t = (lane < 8) ? sh[lane] : 0.0f;
    t = warpSum(t);
    __shared__ float bres;
    if (threadIdx.x == 0) bres = t;
    __syncthreads();
    float r = bres;
    __syncthreads();
    return r;
}

// ================= batch + segments =================
__global__ void batch_convert_kernel(const int* __restrict__ p) {
    int i = blockIdx.x * blockDim.x + threadIdx.x;
    if (i >= NROWS) return;
    int is64 = (__ldg(p + (NROWS - 1)) == 0);
    g_batch[i] = is64 ? __ldg(p + 2 * i) : __ldg(p + i);
}
__global__ void seg_kernel() {
    int i = blockIdx.x * blockDim.x + threadIdx.x;
    if (i >= NROWS) return;
    int v = g_batch[i];
    int lo = 0, hi = NROWS;
    while (lo < hi) { int mid = (lo + hi) >> 1; if (g_batch[mid] < v) lo = mid + 1; else hi = mid; }
    g_segs[i] = lo;
    lo = 0; hi = NROWS;
    while (lo < hi) { int mid = (lo + hi) >> 1; if (g_batch[mid] <= v) lo = mid + 1; else hi = mid; }
    g_sege[i] = lo;
}

// ================= split helpers =================
__device__ __forceinline__ void split2(float v, __nv_bfloat16& hi, __nv_bfloat16& lo) {
    hi = __float2bfloat16(v);
    lo = __float2bfloat16(v - __bfloat162float(hi));
}

__global__ __launch_bounds__(256) void w_split_all(const float* __restrict__ W1,
                                                   const float* __restrict__ W2,
                                                   const float* __restrict__ W3,
                                                   const float* __restrict__ W4,
                                                   __nv_bfloat16* __restrict__ wh,
                                                   __nv_bfloat16* __restrict__ wl) {
    int id = blockIdx.x * 256 + threadIdx.x;
    int w = id >> 16;
    int j = id & 65535;
    const float* src = (w == 0) ? W1 : (w == 1) ? W2 : (w == 2) ? W3 : W4;
    float4 v = ((const float4*)src)[j];
    __nv_bfloat16 h0, l0, h1, l1, h2, l2, h3, l3;
    split2(v.x, h0, l0); split2(v.y, h1, l1);
    split2(v.z, h2, l2); split2(v.w, h3, l3);
    size_t base = (size_t)w * DDIM * DDIM + (size_t)j * 4;
    __nv_bfloat162* ph = (__nv_bfloat162*)(wh + base);
    __nv_bfloat162* pl = (__nv_bfloat162*)(wl + base);
    ph[0] = __nv_bfloat162(h0, h1); ph[1] = __nv_bfloat162(h2, h3);
    pl[0] = __nv_bfloat162(l0, l1); pl[1] = __nv_bfloat162(l2, l3);
}

// ================= LayerNorm =================
__global__ __launch_bounds__(256) void ln_split_kernel(const float* __restrict__ x,
                                                       const float* __restrict__ w,
                                                       const float* __restrict__ b,
                                                       __nv_bfloat16* __restrict__ sh_,
                                                       __nv_bfloat16* __restrict__ sl_) {
    int row = blockIdx.x, t = threadIdx.x;
    const float* xr = x + (size_t)row * DDIM;
    float v0 = xr[t], v1 = xr[t + 256];
    float mu = blockSum256(v0 + v1) * (1.0f / DDIM);
    float d0 = v0 - mu, d1 = v1 - mu;
    float var = blockSum256(d0 * d0 + d1 * d1) * (1.0f / DDIM);
    float r = rsqrtf(var + EPS);
    float y0 = d0 * r * w[t]       + b[t];
    float y1 = d1 * r * w[t + 256] + b[t + 256];
    __nv_bfloat16 h, l;
    size_t base = (size_t)row * DDIM;
    split2(y0, h, l); sh_[base + t] = h;       sl_[base + t] = l;
    split2(y1, h, l); sh_[base + t + 256] = h; sl_[base + t + 256] = l;
}

__global__ __launch_bounds__(256) void ln_kernel(const float* __restrict__ x,
                                                 const float* __restrict__ w,
                                                 const float* __restrict__ b,
                                                 float* __restrict__ y) {
    int row = blockIdx.x, t = threadIdx.x;
    const float* xr = x + (size_t)row * DDIM;
    float v0 = xr[t], v1 = xr[t + 256];
    float mu = blockSum256(v0 + v1) * (1.0f / DDIM);
    float d0 = v0 - mu, d1 = v1 - mu;
    float var = blockSum256(d0 * d0 + d1 * d1) * (1.0f / DDIM);
    float r = rsqrtf(var + EPS);
    float* yr = y + (size_t)row * DDIM;
    yr[t]       = d0 * r * w[t]       + b[t];
    yr[t + 256] = d1 * r * w[t + 256] + b[t + 256];
}

// ================= mma.sync bf16-split GEMM =================
// C[8192,512] = A @ B^T via Ah*Bh + Ah*Bl + Al*Bh, fp32 accum.
// BM=128, BN=128, BK=32. 8 warps (4m x 2n), warp tile 32x64, m16n8k16.
// 3-stage cp.async pipeline; XOR-swizzled 64B rows (conflict-free ldmatrix).
// Stage layout (32KB): Ah[8K] Al[8K] Bh[8K] Bl[8K]; 3 stages = 96KB dynamic smem.
#define GM_STAGE 32768
#define GM_SMEM  (3 * GM_STAGE)

__device__ __forceinline__ uint32_t swz(int row, int c16) {
    return (uint32_t)(row * 64 + ((c16 ^ ((row >> 1) & 3)) << 4));
}

__global__ __launch_bounds__(256, 1) void gemm_mma(const __nv_bfloat16* __restrict__ Ah,
                                                   const __nv_bfloat16* __restrict__ Al,
                                                   const __nv_bfloat16* __restrict__ Bh,
                                                   const __nv_bfloat16* __restrict__ Bl,
                                                   float* __restrict__ C) {
    extern __shared__ char smem[];
    const uint32_t sbase = smem_u32(smem);
    const int tid  = threadIdx.x;
    const int lane = tid & 31;
    const int wid  = tid >> 5;
    const int wm   = wid >> 1;          // 0..3
    const int wn   = wid & 1;           // 0..1
    const int bm   = blockIdx.y * 128;
    const int bn   = blockIdx.x * 128;

    float acc[2][8][4];
    #pragma unroll
    for (int mi = 0; mi < 2; mi++)
        #pragma unroll
        for (int nj = 0; nj < 8; nj++)
            #pragma unroll
            for (int c = 0; c < 4; c++) acc[mi][nj][c] = 0.0f;

    // per-thread load coords (2 chunks of 16B per tile per stage)
    const int id0 = tid, id1 = tid + 256;
    const int lr0 = id0 >> 2, lc0 = id0 & 3;
    const int lr1 = id1 >> 2, lc1 = id1 & 3;
    const uint32_t so0 = swz(lr0, lc0), so1 = swz(lr1, lc1);

    // ldmatrix per-lane coords
    const int arow = (lane & 15);               // + wm*32 + mi*16
    const int acol = (lane >> 4);               // + ks*2
    const int brow = (lane & 7) + ((lane >> 4) & 1) * 8;  // + wn*64 + njp*8
    const int bcol = (lane >> 3) & 1;           // + ks*2

    #define GM_ISSUE(st, kt) do { \
        uint32_t sb_ = sbase + (st) * GM_STAGE; \
        int k0_ = (kt) * 32; \
        size_t ga0 = (size_t)(bm + lr0) * DDIM + k0_ + lc0 * 8; \
        size_t gb0 = (size_t)(bn + lr0) * DDIM + k0_ + lc0 * 8; \
        size_t ga1 = (size_t)(bm + lr1) * DDIM + k0_ + lc1 * 8; \
        size_t gb1 = (size_t)(bn + lr1) * DDIM + k0_ + lc1 * 8; \
        CP_ASYNC16(sb_ + so0,         Ah + ga0); \
        CP_ASYNC16(sb_ + 8192 + so0,  Al + ga0); \
        CP_ASYNC16(sb_ + 16384 + so0, Bh + gb0); \
        CP_ASYNC16(sb_ + 24576 + so0, Bl + gb0); \
        CP_ASYNC16(sb_ + so1,         Ah + ga1); \
        CP_ASYNC16(sb_ + 8192 + so1,  Al + ga1); \
        CP_ASYNC16(sb_ + 16384 + so1, Bh + gb1); \
        CP_ASYNC16(sb_ + 24576 + so1, Bl + gb1); \
    } while (0)

    GM_ISSUE(0, 0); CP_COMMIT();
    GM_ISSUE(1, 1); CP_COMMIT();

    for (int kt = 0; kt < 16; kt++) {
        if (kt < 14) CP_WAIT(1); else CP_WAIT(0);
        __syncthreads();
        const uint32_t sb = sbase + (kt % 3) * GM_STAGE;

        #pragma unroll
        for (int ks = 0; ks < 2; ks++) {
            uint32_t fah[2][4], fal[2][4];
            #pragma unroll
            for (int mi = 0; mi < 2; mi++) {
                uint32_t off = swz(wm * 32 + mi * 16 + arow, ks * 2 + acol);
                LDMX4(fah[mi], sb + off);
                LDMX4(fal[mi], sb + 8192 + off);
            }
            #pragma unroll
            for (int njp = 0; njp < 8; njp += 2) {
                uint32_t off = swz(wn * 64 + njp * 8 + brow, ks * 2 + bcol);
                uint32_t fbh[4], fbl[4];
                LDMX4(fbh, sb + 16384 + off);
                LDMX4(fbl, sb + 24576 + off);
                #pragma unroll
                for (int mi = 0; mi < 2; mi++) {
                    MMA16816(acc[mi][njp],     fah[mi], fbh[0], fbh[1]);
                    MMA16816(acc[mi][njp + 1], fah[mi], fbh[2], fbh[3]);
                    MMA16816(acc[mi][njp],     fah[mi], fbl[0], fbl[1]);
                    MMA16816(acc[mi][njp + 1], fah[mi], fbl[2], fbl[3]);
                    MMA16816(acc[mi][njp],     fal[mi], fbh[0], fbh[1]);
                    MMA16816(acc[mi][njp + 1], fal[mi], fbh[2], fbh[3]);
                }
            }
        }
        if (kt + 2 < 16) { GM_ISSUE((kt + 2) % 3, kt + 2); CP_COMMIT(); }
    }

    // epilogue: direct STG; each instruction covers full 32B sectors per row
    const int erow = lane >> 2;
    const int ecol = (lane & 3) * 2;
    #pragma unroll
    for (int mi = 0; mi < 2; mi++) {
        #pragma unroll
        for (int nj = 0; nj < 8; nj++) {
            int m0 = bm + wm * 32 + mi * 16 + erow;
            int n0 = bn + wn * 64 + nj * 8 + ecol;
            float2 v0 = make_float2(acc[mi][nj][0], acc[mi][nj][1]);
            float2 v1 = make_float2(acc[mi][nj][2], acc[mi][nj][3]);
            *(float2*)(C + (size_t)m0 * DDIM + n0)       = v0;
            *(float2*)(C + (size_t)(m0 + 8) * DDIM + n0) = v1;
        }
    }
}

// ================= GEMM epilogues =================
__global__ __launch_bounds__(256) void epi_silu_split(const float* __restrict__ C,
                                                      const float* __restrict__ bias,
                                                      __nv_bfloat16* __restrict__ sh_,
                                                      __nv_bfloat16* __restrict__ sl_) {
    int i = blockIdx.x * 256 + threadIdx.x;
    float v = C[i] + bias[i & (DDIM - 1)];
    v = v / (1.0f + expf(-v));
    __nv_bfloat16 h, l;
    split2(v, h, l);
    sh_[i] = h; sl_[i] = l;
}
__global__ __launch_bounds__(256) void epi_silu_inplace(float* __restrict__ C,
                                                        const float* __restrict__ bias) {
    int i = blockIdx.x * 256 + threadIdx.x;
    float v = C[i] + bias[i & (DDIM - 1)];
    C[i] = v / (1.0f + expf(-v));
}

// ================= attention =================
__global__ __launch_bounds__(256) void attn_softmax8(const float* __restrict__ q,
                                                     const float* __restrict__ kmat,
                                                     float* __restrict__ attn) {
    int wid = threadIdx.x >> 5, lane = threadIdx.x & 31;
    int i = blockIdx.x * 8 + wid;
    const float* qr = q + (size_t)i * DDIM + lane * 16;
    float4 q0 = *(const float4*)(qr + 0);
    float4 q1 = *(const float4*)(qr + 4);
    float4 q2 = *(const float4*)(qr + 8);
    float4 q3 = *(const float4*)(qr + 12);

    int s = g_segs[i], e = g_sege[i];
    float* row = attn + (size_t)i * NROWS;

    float m = 0.0f;
    for (int j = s; j < e; j++) {
        const float* kr = kmat + (size_t)j * DDIM + lane * 16;
        float4 k0 = *(const float4*)(kr + 0);
        float4 k1 = *(const float4*)(kr + 4);
        float4 k2 = *(const float4*)(kr + 8);
        float4 k3 = *(const float4*)(kr + 12);
        float d = q0.x * k0.x;
        d = fmaf(q0.y, k0.y, d); d = fmaf(q0.z, k0.z, d); d = fmaf(q0.w, k0.w, d);
        d = fmaf(q1.x, k1.x, d); d = fmaf(q1.y, k1.y, d); d = fmaf(q1.z, k1.z, d); d = fmaf(q1.w, k1.w, d);
        d = fmaf(q2.x, k2.x, d); d = fmaf(q2.y, k2.y, d); d = fmaf(q2.z, k2.z, d); d = fmaf(q2.w, k2.w, d);
        d = fmaf(q3.x, k3.x, d); d = fmaf(q3.y, k3.y, d); d = fmaf(q3.z, k3.z, d); d = fmaf(q3.w, k3.w, d);
        d = warpSum(d);
        if (lane == 0) row[j] = d;
        m = fmaxf(m, d);
    }
    __syncwarp();
    m = fmaxf(m, 0.0f);

    float ssum = 0.0f;
    for (int j = s + lane; j < e; j += 32) {
        float ev = expf(row[j] - m);
        ssum += ev;
        row[j] = ev;
    }
    ssum = warpSum(ssum);
    float inv = 1.0f / ssum;
    for (int j = s + lane; j < e; j += 32) row[j] *= inv;
}

__global__ __launch_bounds__(256) void attn_apply8(const float* __restrict__ attn,
                                                   const float* __restrict__ xc,
                                                   __nv_bfloat16* __restrict__ sh_,
                                                   __nv_bfloat16* __restrict__ sl_) {
    int wid = threadIdx.x >> 5, lane = threadIdx.x & 31;
    int i = blockIdx.x * 8 + wid;
    int s = g_segs[i], e = g_sege[i];
    const float* row = attn + (size_t)i * NROWS;
    float acc[16];
    #pragma unroll
    for (int c = 0; c < 16; c++) acc[c] = 0.0f;
    for (int j = s; j < e; j++) {
        float a = __ldg(row + j);
        const float* xr = xc + (size_t)j * DDIM + lane * 16;
        float4 v0 = *(const float4*)(xr + 0);
        float4 v1 = *(const float4*)(xr + 4);
        float4 v2 = *(const float4*)(xr + 8);
        float4 v3 = *(const float4*)(xr + 12);
        acc[0]  = fmaf(a, v0.x, acc[0]);  acc[1]  = fmaf(a, v0.y, acc[1]);
        acc[2]  = fmaf(a, v0.z, acc[2]);  acc[3]  = fmaf(a, v0.w, acc[3]);
        acc[4]  = fmaf(a, v1.x, acc[4]);  acc[5]  = fmaf(a, v1.y, acc[5]);
        acc[6]  = fmaf(a, v1.z, acc[6]);  acc[7]  = fmaf(a, v1.w, acc[7]);
        acc[8]  = fmaf(a, v2.x, acc[8]);  acc[9]  = fmaf(a, v2.y, acc[9]);
        acc[10] = fmaf(a, v2.z, acc[10]); acc[11] = fmaf(a, v2.w, acc[11]);
        acc[12] = fmaf(a, v3.x, acc[12]); acc[13] = fmaf(a, v3.y, acc[13]);
        acc[14] = fmaf(a, v3.z, acc[14]); acc[15] = fmaf(a, v3.w, acc[15]);
    }
    size_t base = (size_t)i * DDIM + lane * 16;
    #pragma unroll
    for (int c = 0; c < 16; c++) {
        __nv_bfloat16 h, l;
        split2(acc[c], h, l);
        sh_[base + c] = h; sl_[base + c] = l;
    }
}

// ================= launch =================
extern "C" void kernel_launch(void* const* d_in, const int* in_sizes, int n_in,
                              void* d_out, int out_size) {
    const float* x_mole  = (const float*)d_in[0];
    const float* x_conf  = (const float*)d_in[1];
    const float* W1      = (const float*)d_in[2];
    const float* W2      = (const float*)d_in[3];
    const float* phi1_w  = (const float*)d_in[4];
    const float* phi1_b  = (const float*)d_in[5];
    const float* phi2_w  = (const float*)d_in[6];
    const float* phi2_b  = (const float*)d_in[7];
    const float* rho_w1  = (const float*)d_in[8];
    const float* rho_b1  = (const float*)d_in[9];
    const float* rho_w2  = (const float*)d_in[10];
    const float* rho_b2  = (const float*)d_in[11];
    const float* rho_ln_w = (const float*)d_in[12];
    const float* rho_ln_b = (const float*)d_in[13];
    const int*   batch   = (const int*)d_in[14];

    float* out_enc  = (float*)d_out;
    float* out_attn = (float*)d_out + (size_t)NROWS * DDIM;

    float *q, *k;
    __nv_bfloat16 *sh1, *sl1, *sh2, *sl2, *wh, *wl;
    cudaGetSymbolAddress((void**)&q,   g_q);
    cudaGetSymbolAddress((void**)&k,   g_k);
    cudaGetSymbolAddress((void**)&sh1, g_sh1);
    cudaGetSymbolAddress((void**)&sl1, g_sl1);
    cudaGetSymbolAddress((void**)&sh2, g_sh2);
    cudaGetSymbolAddress((void**)&sl2, g_sl2);
    cudaGetSymbolAddress((void**)&wh,  g_wh);
    cudaGetSymbolAddress((void**)&wl,  g_wl);
    const size_t WSZ = (size_t)DDIM * DDIM;

    cudaFuncSetAttribute(gemm_mma, cudaFuncAttributeMaxDynamicSharedMemorySize, GM_SMEM);

    // 1,2: segment metadata
    batch_convert_kernel<<<(NROWS + 255) / 256, 256>>>(batch);
    seg_kernel<<<(NROWS + 255) / 256, 256>>>();

    // 3: weight splits
    w_split_all<<<4 * 65536 / 256, 256>>>(W1, W2, rho_w1, rho_w2, wh, wl);

    // 4,5: LayerNorm + split of both inputs
    ln_split_kernel<<<NROWS, 256>>>(x_mole, phi1_w, phi1_b, sh1, sl1);
    ln_split_kernel<<<NROWS, 256>>>(x_conf, phi2_w, phi2_b, sh2, sl2);

    // 6,7: q/k projections (launch #6 = ncu-profiled)
    dim3 ggrid(DDIM / 128, NROWS / 128);
    gemm_mma<<<ggrid, 256, GM_SMEM>>>(sh1, sl1, wh + 0 * WSZ, wl + 0 * WSZ, q);
    gemm_mma<<<ggrid, 256, GM_SMEM>>>(sh2, sl2, wh + 1 * WSZ, wl + 1 * WSZ, k);

    // 8-10: attn zero + masked softmax + apply
    cudaMemsetAsync(out_attn, 0, (size_t)NROWS * NROWS * sizeof(float));
    attn_softmax8<<<NROWS / 8, 256>>>(q, k, out_attn);
    attn_apply8<<<NROWS / 8, 256>>>(out_attn, x_conf, sh1, sl1);

    // 11-14: rho MLP
    int egrid = (int)((size_t)NROWS * DDIM / 256);
    gemm_mma<<<ggrid, 256, GM_SMEM>>>(sh1, sl1, wh + 2 * WSZ, wl + 2 * WSZ, q);
    epi_silu_split<<<egrid, 256>>>(q, rho_b1, sh2, sl2);
    gemm_mma<<<ggrid, 256, GM_SMEM>>>(sh2, sl2, wh + 3 * WSZ, wl + 3 * WSZ, k);
    epi_silu_inplace<<<egrid, 256>>>(k, rho_b2);

    // 15: final LayerNorm into output
    ln_kernel<<<NROWS, 256>>>(k, rho_ln_w, rho_ln_b, out_enc);
}

// round 6
// speedup vs baseline: 2.5013x; 1.8364x over previous
#include <cuda_runtime.h>
#include <cuda_bf16.h>
#include <math.h>
#include <stdint.h>

#define NROWS 8192
#define DDIM  512
#define EPS   1e-5f

// ================= PTX helpers (sm_103 base-target safe: no tcgen05) =================
__device__ __forceinline__ uint32_t smem_u32(const void* p) {
    uint32_t a;
    asm("{ .reg .u64 t; cvta.to.shared.u64 t, %1; cvt.u32.u64 %0, t; }" : "=r"(a) : "l"(p));
    return a;
}
#define CP_ASYNC16(smem, gptr) \
    asm volatile("cp.async.cg.shared.global [%0], [%1], 16;" :: "r"(smem), "l"(gptr))
#define CP_COMMIT() asm volatile("cp.async.commit_group;" ::: "memory")
#define CP_WAIT(n)  asm volatile("cp.async.wait_group %0;" :: "n"(n) : "memory")

#define LDMX4(r, addr) \
    asm volatile("ldmatrix.sync.aligned.m8n8.x4.shared.b16 {%0,%1,%2,%3}, [%4];" \
        : "=r"((r)[0]), "=r"((r)[1]), "=r"((r)[2]), "=r"((r)[3]) : "r"(addr))

#define MMA16816(d, a, b0, b1) \
    asm volatile("mma.sync.aligned.m16n8k16.row.col.f32.bf16.bf16.f32 " \
        "{%0,%1,%2,%3}, {%4,%5,%6,%7}, {%8,%9}, {%0,%1,%2,%3};" \
        : "+f"((d)[0]), "+f"((d)[1]), "+f"((d)[2]), "+f"((d)[3]) \
        : "r"((a)[0]), "r"((a)[1]), "r"((a)[2]), "r"((a)[3]), "r"(b0), "r"(b1))

// ================= scratch =================
__device__ float g_q  [NROWS * DDIM];
__device__ float g_k  [NROWS * DDIM];
__device__ __nv_bfloat16 g_sh1[NROWS * DDIM];
__device__ __nv_bfloat16 g_sl1[NROWS * DDIM];
__device__ __nv_bfloat16 g_sh2[NROWS * DDIM];
__device__ __nv_bfloat16 g_sl2[NROWS * DDIM];
__device__ __nv_bfloat16 g_wh[4][DDIM * DDIM];
__device__ __nv_bfloat16 g_wl[4][DDIM * DDIM];
__device__ int   g_batch[NROWS];
__device__ int   g_segs[NROWS];
__device__ int   g_sege[NROWS];

// ================= reductions =================
__device__ __forceinline__ float warpSum(float v) {
    #pragma unroll
    for (int o = 16; o > 0; o >>= 1) v += __shfl_xor_sync(0xffffffffu, v, o);
    return v;
}
__device__ float blockSum256(float v) {
    __shared__ float sh[8];
    int lane = threadIdx.x & 31, w = threadIdx.x >> 5;
    v = warpSum(v);
    if (lane == 0) sh[w] = v;
    __syncthreads();
    float t = (lane < 8) ? sh[lane] : 0.0f;
    t = warpSum(t);
    __shared__ float bres;
    if (threadIdx.x == 0) bres = t;
    __syncthreads();
    float r = bres;
    __syncthreads();
    return r;
}

// ================= batch + segments =================
__global__ void batch_convert_kernel(const int* __restrict__ p) {
    int i = blockIdx.x * blockDim.x + threadIdx.x;
    if (i >= NROWS) return;
    int is64 = (__ldg(p + (NROWS - 1)) == 0);
    g_batch[i] = is64 ? __ldg(p + 2 * i) : __ldg(p + i);
}
__global__ void seg_kernel() {
    int i = blockIdx.x * blockDim.x + threadIdx.x;
    if (i >= NROWS) return;
    int v = g_batch[i];
    int lo = 0, hi = NROWS;
    while (lo < hi) { int mid = (lo + hi) >> 1; if (g_batch[mid] < v) lo = mid + 1; else hi = mid; }
    g_segs[i] = lo;
    lo = 0; hi = NROWS;
    while (lo < hi) { int mid = (lo + hi) >> 1; if (g_batch[mid] <= v) lo = mid + 1; else hi = mid; }
    g_sege[i] = lo;
}

// ================= split helpers =================
__device__ __forceinline__ void split2(float v, __nv_bfloat16& hi, __nv_bfloat16& lo) {
    hi = __float2bfloat16(v);
    lo = __float2bfloat16(v - __bfloat162float(hi));
}

__global__ __launch_bounds__(256) void w_split_all(const float* __restrict__ W1,
                                                   const float* __restrict__ W2,
                                                   const float* __restrict__ W3,
                                                   const float* __restrict__ W4,
                                                   __nv_bfloat16* __restrict__ wh,
                                                   __nv_bfloat16* __restrict__ wl) {
    int id = blockIdx.x * 256 + threadIdx.x;
    int w = id >> 16;
    int j = id & 65535;
    const float* src = (w == 0) ? W1 : (w == 1) ? W2 : (w == 2) ? W3 : W4;
    float4 v = ((const float4*)src)[j];
    __nv_bfloat16 h0, l0, h1, l1, h2, l2, h3, l3;
    split2(v.x, h0, l0); split2(v.y, h1, l1);
    split2(v.z, h2, l2); split2(v.w, h3, l3);
    size_t base = (size_t)w * DDIM * DDIM + (size_t)j * 4;
    __nv_bfloat162* ph = (__nv_bfloat162*)(wh + base);
    __nv_bfloat162* pl = (__nv_bfloat162*)(wl + base);
    ph[0] = __nv_bfloat162(h0, h1); ph[1] = __nv_bfloat162(h2, h3);
    pl[0] = __nv_bfloat162(l0, l1); pl[1] = __nv_bfloat162(l2, l3);
}

// ================= LayerNorm =================
__global__ __launch_bounds__(256) void ln_split_kernel(const float* __restrict__ x,
                                                       const float* __restrict__ w,
                                                       const float* __restrict__ b,
                                                       __nv_bfloat16* __restrict__ sh_,
                                                       __nv_bfloat16* __restrict__ sl_) {
    int row = blockIdx.x, t = threadIdx.x;
    const float* xr = x + (size_t)row * DDIM;
    float v0 = xr[t], v1 = xr[t + 256];
    float mu = blockSum256(v0 + v1) * (1.0f / DDIM);
    float d0 = v0 - mu, d1 = v1 - mu;
    float var = blockSum256(d0 * d0 + d1 * d1) * (1.0f / DDIM);
    float r = rsqrtf(var + EPS);
    float y0 = d0 * r * w[t]       + b[t];
    float y1 = d1 * r * w[t + 256] + b[t + 256];
    __nv_bfloat16 h, l;
    size_t base = (size_t)row * DDIM;
    split2(y0, h, l); sh_[base + t] = h;       sl_[base + t] = l;
    split2(y1, h, l); sh_[base + t + 256] = h; sl_[base + t + 256] = l;
}

__global__ __launch_bounds__(256) void ln_kernel(const float* __restrict__ x,
                                                 const float* __restrict__ w,
                                                 const float* __restrict__ b,
                                                 float* __restrict__ y) {
    int row = blockIdx.x, t = threadIdx.x;
    const float* xr = x + (size_t)row * DDIM;
    float v0 = xr[t], v1 = xr[t + 256];
    float mu = blockSum256(v0 + v1) * (1.0f / DDIM);
    float d0 = v0 - mu, d1 = v1 - mu;
    float var = blockSum256(d0 * d0 + d1 * d1) * (1.0f / DDIM);
    float r = rsqrtf(var + EPS);
    float* yr = y + (size_t)row * DDIM;
    yr[t]       = d0 * r * w[t]       + b[t];
    yr[t + 256] = d1 * r * w[t + 256] + b[t + 256];
}

// ================= mma.sync bf16-split GEMM =================
// BM=128, BN=128, BK=32, 8 warps, 3-stage cp.async pipeline, swizzled 64B rows.
#define GM_STAGE 32768
#define GM_SMEM  (3 * GM_STAGE)

__device__ __forceinline__ uint32_t swz(int row, int c16) {
    return (uint32_t)(row * 64 + ((c16 ^ ((row >> 1) & 3)) << 4));
}

__global__ __launch_bounds__(256, 1) void gemm_mma(const __nv_bfloat16* __restrict__ Ah,
                                                   const __nv_bfloat16* __restrict__ Al,
                                                   const __nv_bfloat16* __restrict__ Bh,
                                                   const __nv_bfloat16* __restrict__ Bl,
                                                   float* __restrict__ C) {
    extern __shared__ char smem[];
    const uint32_t sbase = smem_u32(smem);
    const int tid  = threadIdx.x;
    const int lane = tid & 31;
    const int wid  = tid >> 5;
    const int wm   = wid >> 1;
    const int wn   = wid & 1;
    const int bm   = blockIdx.y * 128;
    const int bn   = blockIdx.x * 128;

    float acc[2][8][4];
    #pragma unroll
    for (int mi = 0; mi < 2; mi++)
        #pragma unroll
        for (int nj = 0; nj < 8; nj++)
            #pragma unroll
            for (int c = 0; c < 4; c++) acc[mi][nj][c] = 0.0f;

    const int id0 = tid, id1 = tid + 256;
    const int lr0 = id0 >> 2, lc0 = id0 & 3;
    const int lr1 = id1 >> 2, lc1 = id1 & 3;
    const uint32_t so0 = swz(lr0, lc0), so1 = swz(lr1, lc1);

    const int arow = (lane & 15);
    const int acol = (lane >> 4);
    const int brow = (lane & 7) + ((lane >> 4) & 1) * 8;
    const int bcol = (lane >> 3) & 1;

    #define GM_ISSUE(st, kt) do { \
        uint32_t sb_ = sbase + (st) * GM_STAGE; \
        int k0_ = (kt) * 32; \
        size_t ga0 = (size_t)(bm + lr0) * DDIM + k0_ + lc0 * 8; \
        size_t gb0 = (size_t)(bn + lr0) * DDIM + k0_ + lc0 * 8; \
        size_t ga1 = (size_t)(bm + lr1) * DDIM + k0_ + lc1 * 8; \
        size_t gb1 = (size_t)(bn + lr1) * DDIM + k0_ + lc1 * 8; \
        CP_ASYNC16(sb_ + so0,         Ah + ga0); \
        CP_ASYNC16(sb_ + 8192 + so0,  Al + ga0); \
        CP_ASYNC16(sb_ + 16384 + so0, Bh + gb0); \
        CP_ASYNC16(sb_ + 24576 + so0, Bl + gb0); \
        CP_ASYNC16(sb_ + so1,         Ah + ga1); \
        CP_ASYNC16(sb_ + 8192 + so1,  Al + ga1); \
        CP_ASYNC16(sb_ + 16384 + so1, Bh + gb1); \
        CP_ASYNC16(sb_ + 24576 + so1, Bl + gb1); \
    } while (0)

    GM_ISSUE(0, 0); CP_COMMIT();
    GM_ISSUE(1, 1); CP_COMMIT();

    for (int kt = 0; kt < 16; kt++) {
        if (kt < 14) CP_WAIT(1); else CP_WAIT(0);
        __syncthreads();
        const uint32_t sb = sbase + (kt % 3) * GM_STAGE;

        #pragma unroll
        for (int ks = 0; ks < 2; ks++) {
            uint32_t fah[2][4], fal[2][4];
            #pragma unroll
            for (int mi = 0; mi < 2; mi++) {
                uint32_t off = swz(wm * 32 + mi * 16 + arow, ks * 2 + acol);
                LDMX4(fah[mi], sb + off);
                LDMX4(fal[mi], sb + 8192 + off);
            }
            #pragma unroll
            for (int njp = 0; njp < 8; njp += 2) {
                uint32_t off = swz(wn * 64 + njp * 8 + brow, ks * 2 + bcol);
                uint32_t fbh[4], fbl[4];
                LDMX4(fbh, sb + 16384 + off);
                LDMX4(fbl, sb + 24576 + off);
                #pragma unroll
                for (int mi = 0; mi < 2; mi++) {
                    MMA16816(acc[mi][njp],     fah[mi], fbh[0], fbh[1]);
                    MMA16816(acc[mi][njp + 1], fah[mi], fbh[2], fbh[3]);
                    MMA16816(acc[mi][njp],     fah[mi], fbl[0], fbl[1]);
                    MMA16816(acc[mi][njp + 1], fah[mi], fbl[2], fbl[3]);
                    MMA16816(acc[mi][njp],     fal[mi], fbh[0], fbh[1]);
                    MMA16816(acc[mi][njp + 1], fal[mi], fbh[2], fbh[3]);
                }
            }
        }
        if (kt + 2 < 16) { GM_ISSUE((kt + 2) % 3, kt + 2); CP_COMMIT(); }
    }

    const int erow = lane >> 2;
    const int ecol = (lane & 3) * 2;
    #pragma unroll
    for (int mi = 0; mi < 2; mi++) {
        #pragma unroll
        for (int nj = 0; nj < 8; nj++) {
            int m0 = bm + wm * 32 + mi * 16 + erow;
            int n0 = bn + wn * 64 + nj * 8 + ecol;
            float2 v0 = make_float2(acc[mi][nj][0], acc[mi][nj][1]);
            float2 v1 = make_float2(acc[mi][nj][2], acc[mi][nj][3]);
            *(float2*)(C + (size_t)m0 * DDIM + n0)       = v0;
            *(float2*)(C + (size_t)(m0 + 8) * DDIM + n0) = v1;
        }
    }
}

// ================= GEMM epilogues =================
__global__ __launch_bounds__(256) void epi_silu_split(const float* __restrict__ C,
                                                      const float* __restrict__ bias,
                                                      __nv_bfloat16* __restrict__ sh_,
                                                      __nv_bfloat16* __restrict__ sl_) {
    int i = blockIdx.x * 256 + threadIdx.x;
    float v = C[i] + bias[i & (DDIM - 1)];
    v = v / (1.0f + expf(-v));
    __nv_bfloat16 h, l;
    split2(v, h, l);
    sh_[i] = h; sl_[i] = l;
}
__global__ __launch_bounds__(256) void epi_silu_inplace(float* __restrict__ C,
                                                        const float* __restrict__ bias) {
    int i = blockIdx.x * 256 + threadIdx.x;
    float v = C[i] + bias[i & (DDIM - 1)];
    C[i] = v / (1.0f + expf(-v));
}

// ================= tiled attention =================
// 16 rows per block (warp-per-row, 512 thr). K / x_conf staged through a
// 32-row x 512-f32 smem tile (64KB dynamic) shared by all 16 rows -> L2
// traffic cut 16x vs per-row streaming. Lane owns cols lane*4 + c*128
// (contiguous 128B per 8-lane phase -> conflict-free LDS.128).
#define AT_TILE  32
#define AT_SMEM  (AT_TILE * DDIM * 4)

__global__ __launch_bounds__(512) void attn_softmax16(const float* __restrict__ q,
                                                      const float* __restrict__ kmat,
                                                      float* __restrict__ attn) {
    extern __shared__ float ktile[];
    const int tid = threadIdx.x, wid = tid >> 5, lane = tid & 31;
    const int i = blockIdx.x * 16 + wid;
    const int s = g_segs[i], e = g_sege[i];
    const int sb = g_segs[blockIdx.x * 16];
    const int eb = g_sege[blockIdx.x * 16 + 15];

    const float* qr = q + (size_t)i * DDIM;
    float4 qv[4];
    #pragma unroll
    for (int c = 0; c < 4; c++) qv[c] = *(const float4*)(qr + c * 128 + lane * 4);

    float* row = attn + (size_t)i * NROWS;
    float m = 0.0f;

    for (int t = sb; t < eb; t += AT_TILE) {
        const int tn = min(AT_TILE, eb - t);
        __syncthreads();
        for (int idx = tid; idx < tn * 128; idx += 512) {
            int r = idx >> 7, c = idx & 127;
            *(float4*)(ktile + r * DDIM + c * 4) = *(const float4*)(kmat + (size_t)(t + r) * DDIM + c * 4);
        }
        __syncthreads();
        const int j0 = max(s, t), j1 = min(e, t + tn);
        for (int j = j0; j < j1; j++) {
            const float* kr = ktile + (j - t) * DDIM;
            float4 k0 = *(const float4*)(kr + 0 * 128 + lane * 4);
            float4 k1 = *(const float4*)(kr + 1 * 128 + lane * 4);
            float4 k2 = *(const float4*)(kr + 2 * 128 + lane * 4);
            float4 k3 = *(const float4*)(kr + 3 * 128 + lane * 4);
            float d = qv[0].x * k0.x;
            d = fmaf(qv[0].y, k0.y, d); d = fmaf(qv[0].z, k0.z, d); d = fmaf(qv[0].w, k0.w, d);
            d = fmaf(qv[1].x, k1.x, d); d = fmaf(qv[1].y, k1.y, d); d = fmaf(qv[1].z, k1.z, d); d = fmaf(qv[1].w, k1.w, d);
            d = fmaf(qv[2].x, k2.x, d); d = fmaf(qv[2].y, k2.y, d); d = fmaf(qv[2].z, k2.z, d); d = fmaf(qv[2].w, k2.w, d);
            d = fmaf(qv[3].x, k3.x, d); d = fmaf(qv[3].y, k3.y, d); d = fmaf(qv[3].z, k3.z, d); d = fmaf(qv[3].w, k3.w, d);
            d = warpSum(d);
            if (lane == 0) row[j] = d;
            m = fmaxf(m, d);
        }
    }
    m = fmaxf(m, 0.0f);   // reference: max over dot*mask includes zeros

    float ssum = 0.0f;
    for (int j = s + lane; j < e; j += 32) {
        float ev = expf(row[j] - m);
        ssum += ev;
        row[j] = ev;
    }
    ssum = warpSum(ssum);
    float inv = 1.0f / ssum;
    for (int j = s + lane; j < e; j += 32) row[j] *= inv;
}

__global__ __launch_bounds__(512) void attn_apply16(const float* __restrict__ attn,
                                                    const float* __restrict__ xc,
                                                    __nv_bfloat16* __restrict__ sh_,
                                                    __nv_bfloat16* __restrict__ sl_) {
    extern __shared__ float xtile[];
    const int tid = threadIdx.x, wid = tid >> 5, lane = tid & 31;
    const int i = blockIdx.x * 16 + wid;
    const int s = g_segs[i], e = g_sege[i];
    const int sb = g_segs[blockIdx.x * 16];
    const int eb = g_sege[blockIdx.x * 16 + 15];
    const float* row = attn + (size_t)i * NROWS;

    float4 acc[4];
    #pragma unroll
    for (int c = 0; c < 4; c++) acc[c] = make_float4(0.f, 0.f, 0.f, 0.f);

    for (int t = sb; t < eb; t += AT_TILE) {
        const int tn = min(AT_TILE, eb - t);
        __syncthreads();
        for (int idx = tid; idx < tn * 128; idx += 512) {
            int r = idx >> 7, c = idx & 127;
            *(float4*)(xtile + r * DDIM + c * 4) = *(const float4*)(xc + (size_t)(t + r) * DDIM + c * 4);
        }
        __syncthreads();
        const int j0 = max(s, t), j1 = min(e, t + tn);
        for (int j = j0; j < j1; j++) {
            float a = __ldg(row + j);
            const float* xr = xtile + (j - t) * DDIM;
            #pragma unroll
            for (int c = 0; c < 4; c++) {
                float4 v = *(const float4*)(xr + c * 128 + lane * 4);
                acc[c].x = fmaf(a, v.x, acc[c].x);
                acc[c].y = fmaf(a, v.y, acc[c].y);
                acc[c].z = fmaf(a, v.z, acc[c].z);
                acc[c].w = fmaf(a, v.w, acc[c].w);
            }
        }
    }

    size_t base = (size_t)i * DDIM;
    #pragma unroll
    for (int c = 0; c < 4; c++) {
        size_t o = base + c * 128 + lane * 4;
        __nv_bfloat16 h, l;
        split2(acc[c].x, h, l); sh_[o + 0] = h; sl_[o + 0] = l;
        split2(acc[c].y, h, l); sh_[o + 1] = h; sl_[o + 1] = l;
        split2(acc[c].z, h, l); sh_[o + 2] = h; sl_[o + 2] = l;
        split2(acc[c].w, h, l); sh_[o + 3] = h; sl_[o + 3] = l;
    }
}

// ================= launch =================
extern "C" void kernel_launch(void* const* d_in, const int* in_sizes, int n_in,
                              void* d_out, int out_size) {
    const float* x_mole  = (const float*)d_in[0];
    const float* x_conf  = (const float*)d_in[1];
    const float* W1      = (const float*)d_in[2];
    const float* W2      = (const float*)d_in[3];
    const float* phi1_w  = (const float*)d_in[4];
    const float* phi1_b  = (const float*)d_in[5];
    const float* phi2_w  = (const float*)d_in[6];
    const float* phi2_b  = (const float*)d_in[7];
    const float* rho_w1  = (const float*)d_in[8];
    const float* rho_b1  = (const float*)d_in[9];
    const float* rho_w2  = (const float*)d_in[10];
    const float* rho_b2  = (const float*)d_in[11];
    const float* rho_ln_w = (const float*)d_in[12];
    const float* rho_ln_b = (const float*)d_in[13];
    const int*   batch   = (const int*)d_in[14];

    float* out_enc  = (float*)d_out;
    float* out_attn = (float*)d_out + (size_t)NROWS * DDIM;

    float *q, *k;
    __nv_bfloat16 *sh1, *sl1, *sh2, *sl2, *wh, *wl;
    cudaGetSymbolAddress((void**)&q,   g_q);
    cudaGetSymbolAddress((void**)&k,   g_k);
    cudaGetSymbolAddress((void**)&sh1, g_sh1);
    cudaGetSymbolAddress((void**)&sl1, g_sl1);
    cudaGetSymbolAddress((void**)&sh2, g_sh2);
    cudaGetSymbolAddress((void**)&sl2, g_sl2);
    cudaGetSymbolAddress((void**)&wh,  g_wh);
    cudaGetSymbolAddress((void**)&wl,  g_wl);
    const size_t WSZ = (size_t)DDIM * DDIM;

    cudaFuncSetAttribute(gemm_mma, cudaFuncAttributeMaxDynamicSharedMemorySize, GM_SMEM);
    cudaFuncSetAttribute(attn_softmax16, cudaFuncAttributeMaxDynamicSharedMemorySize, AT_SMEM);
    cudaFuncSetAttribute(attn_apply16, cudaFuncAttributeMaxDynamicSharedMemorySize, AT_SMEM);

    // segment metadata
    batch_convert_kernel<<<(NROWS + 255) / 256, 256>>>(batch);
    seg_kernel<<<(NROWS + 255) / 256, 256>>>();

    // weight splits
    w_split_all<<<4 * 65536 / 256, 256>>>(W1, W2, rho_w1, rho_w2, wh, wl);

    // LayerNorm + split of both inputs
    ln_split_kernel<<<NROWS, 256>>>(x_mole, phi1_w, phi1_b, sh1, sl1);
    ln_split_kernel<<<NROWS, 256>>>(x_conf, phi2_w, phi2_b, sh2, sl2);

    // q / k projections
    dim3 ggrid(DDIM / 128, NROWS / 128);
    gemm_mma<<<ggrid, 256, GM_SMEM>>>(sh1, sl1, wh + 0 * WSZ, wl + 0 * WSZ, q);
    gemm_mma<<<ggrid, 256, GM_SMEM>>>(sh2, sl2, wh + 1 * WSZ, wl + 1 * WSZ, k);

    // attn zero + tiled masked softmax + tiled apply
    cudaMemsetAsync(out_attn, 0, (size_t)NROWS * NROWS * sizeof(float));
    attn_softmax16<<<NROWS / 16, 512, AT_SMEM>>>(q, k, out_attn);
    attn_apply16<<<NROWS / 16, 512, AT_SMEM>>>(out_attn, x_conf, sh1, sl1);

    // rho MLP
    int egrid = (int)((size_t)NROWS * DDIM / 256);
    gemm_mma<<<ggrid, 256, GM_SMEM>>>(sh1, sl1, wh + 2 * WSZ, wl + 2 * WSZ, q);
    epi_silu_split<<<egrid, 256>>>(q, rho_b1, sh2, sl2);
    gemm_mma<<<ggrid, 256, GM_SMEM>>>(sh2, sl2, wh + 3 * WSZ, wl + 3 * WSZ, k);
    epi_silu_inplace<<<egrid, 256>>>(k, rho_b2);

    // final LayerNorm into output
    ln_kernel<<<NROWS, 256>>>(k, rho_ln_w, rho_ln_b, out_enc);
}